// round 14
// baseline (speedup 1.0000x reference)
#include <cuda_runtime.h>
#include <cuda_fp16.h>
#include <mma.h>
#include <math.h>

using namespace nvcuda;

#define NN 50000
#define NE 800000
#define HD 128
#define NG 64
#define SCAN_BLKS 49   // 49*1024 >= NN
#define LDS 136        // padded smem leading dim (halves / floats)

// ---------------- scratch (device globals: allocation-free) ----------------
__device__ int      g_deg[NN];
__device__ int      g_fill[NN];
__device__ int      g_off[NN + 1];
__device__ int      g_bsum[SCAN_BLKS];
__device__ int2     g_csr[NE];         // packed {src, weight bits}
__device__ __half   g_Sh[NN * HD];     // GEMM output (support), fp16
__device__ __half   g_Xh[NN * HD];     // fp16 copy of input features
__device__ __half   g_Wh[3 * HD * HD]; // fp16 copies of W1,W2,W3
__device__ __half   g_h1[NN * HD];     // layer outputs, fp16
__device__ __half   g_h2[NN * HD];
__device__ __half   g_h3[NN * HD];
__device__ float    g_slin[NN];
__device__ float    g_poolsum[NG * 3 * HD];
__device__ unsigned g_poolmax[NG * 3 * HD];
__device__ int      g_gstart[NG + 1];

// monotonic float<->uint encoding for atomicMax on floats
__device__ __forceinline__ unsigned encf(float f) {
    unsigned u = __float_as_uint(f);
    return (u & 0x80000000u) ? ~u : (u | 0x80000000u);
}
__device__ __forceinline__ float decf(unsigned u) {
    return __uint_as_float((u & 0x80000000u) ? (u ^ 0x80000000u) : ~u);
}

// ---------------- fp32 -> fp16 conversion (vectorized) ---------------------
__global__ void f2h_kernel(const float* __restrict__ in, __half* __restrict__ out, int n4) {
    int i = blockIdx.x * blockDim.x + threadIdx.x;
    if (i >= n4) return;
    float4 v = ((const float4*)in)[i];
    __half2 p0 = __floats2half2_rn(v.x, v.y);
    __half2 p1 = __floats2half2_rn(v.z, v.w);
    uint2 pk;
    pk.x = *(unsigned*)&p0;
    pk.y = *(unsigned*)&p1;
    ((uint2*)out)[i] = pk;
}

// ---------------- init (pool-side; runs off critical path) ----------------
__global__ void zero_pool_kernel() {
    int i = blockIdx.x * blockDim.x + threadIdx.x;
    int stride = gridDim.x * blockDim.x;
    for (int j = i; j < NG * 3 * HD; j += stride) { g_poolsum[j] = 0.f; g_poolmax[j] = 0u; }
    if (i < NG + 1) g_gstart[i] = 0;
}

// ---------------- CSR build (edge_index int32) -----------------------------
// 4 edges per thread via int4
__global__ void hist_kernel(const int* __restrict__ ei) {
    int i = blockIdx.x * blockDim.x + threadIdx.x;
    if (i >= NE / 4) return;
    int4 d4 = ((const int4*)(ei + NE))[i];
    if ((unsigned)d4.x < NN) atomicAdd(&g_deg[d4.x], 1);
    if ((unsigned)d4.y < NN) atomicAdd(&g_deg[d4.y], 1);
    if ((unsigned)d4.z < NN) atomicAdd(&g_deg[d4.z], 1);
    if ((unsigned)d4.w < NN) atomicAdd(&g_deg[d4.w], 1);
}

__global__ void scan_part_kernel() {
    int idx = blockIdx.x * 1024 + threadIdx.x;
    int v = (idx < NN) ? g_deg[idx] : 0;
    int lane = threadIdx.x & 31, wid = threadIdx.x >> 5;
#pragma unroll
    for (int o = 16; o > 0; o >>= 1) v += __shfl_down_sync(0xffffffffu, v, o);
    __shared__ int ws[32];
    if (lane == 0) ws[wid] = v;
    __syncthreads();
    if (wid == 0) {
        int s = ws[lane];
#pragma unroll
        for (int o = 16; o > 0; o >>= 1) s += __shfl_down_sync(0xffffffffu, s, o);
        if (lane == 0) g_bsum[blockIdx.x] = s;
    }
}

__global__ void scan_final_kernel() {
    int t = threadIdx.x;
    int idx = blockIdx.x * 1024 + t;
    int v = (idx < NN) ? g_deg[idx] : 0;
    int lane = t & 31, wid = t >> 5;

    __shared__ int bs[64];
    __shared__ int ws[32];
    __shared__ int base_sh;
    if (t < SCAN_BLKS) bs[t] = g_bsum[t];

    int incl = v;
#pragma unroll
    for (int o = 1; o < 32; o <<= 1) {
        int x = __shfl_up_sync(0xffffffffu, incl, o);
        if (lane >= o) incl += x;
    }
    if (lane == 31) ws[wid] = incl;
    __syncthreads();
    if (wid == 0) {
        int s = (lane < 32) ? ws[lane] : 0;
#pragma unroll
        for (int o = 1; o < 32; o <<= 1) {
            int x = __shfl_up_sync(0xffffffffu, s, o);
            if (lane >= o) s += x;
        }
        ws[lane] = s;
    }
    if (t == 0) {
        int b = 0;
        for (int i = 0; i < blockIdx.x; i++) b += bs[i];
        base_sh = b;
    }
    __syncthreads();
    int warpbase = (wid > 0) ? ws[wid - 1] : 0;
    int excl = base_sh + warpbase + incl - v;
    if (idx < NN) { g_off[idx] = excl; g_fill[idx] = excl; }
    if (blockIdx.x == gridDim.x - 1 && t == 1023) g_off[NN] = base_sh + warpbase + incl;
}

// 2 edges per thread; packed int2 payload write
__global__ void scatter_kernel(const int* __restrict__ ei,
                               const float* __restrict__ ew) {
    int i = blockIdx.x * blockDim.x + threadIdx.x;
    if (i >= NE / 2) return;
    int2 s2 = ((const int2*)ei)[i];
    int2 d2 = ((const int2*)(ei + NE))[i];
    float2 w2 = ((const float2*)ew)[i];
    if ((unsigned)d2.x < NN && (unsigned)s2.x < NN) {
        int pos = atomicAdd(&g_fill[d2.x], 1);
        g_csr[pos] = make_int2(s2.x, __float_as_int(w2.x));
    }
    if ((unsigned)d2.y < NN && (unsigned)s2.y < NN) {
        int pos = atomicAdd(&g_fill[d2.y], 1);
        g_csr[pos] = make_int2(s2.y, __float_as_int(w2.y));
    }
}

__global__ void bounds_kernel(const int* __restrict__ gi) {
    int n = blockIdx.x * blockDim.x + threadIdx.x;
    if (n >= NN) return;
    int g = gi[n];
    if ((unsigned)g >= NG) return;
    if (n == 0) g_gstart[g] = 0;
    else if (gi[n - 1] != g) g_gstart[g] = n;
    if (n == NN - 1) g_gstart[NG] = NN;
}

__global__ void bounds_fix_kernel() {
    if (threadIdx.x == 0) {
        for (int g = NG - 1; g >= 1; g--)
            if (g_gstart[g] == 0 && g_gstart[g - 1] != 0) g_gstart[g] = g_gstart[g + 1];
    }
}

// ---------------- GEMM: Sh = fp16( A(fp16) @ W(fp16) ), fp32 accumulate ---
__global__ void __launch_bounds__(256)
gemm128h_kernel(const __half* __restrict__ A,
                const __half* __restrict__ B,
                __half* __restrict__ S, int nrows) {
    extern __shared__ __half sh[];
    __half* Bs = sh;                 // [128][LDS]
    __half* As = sh + HD * LDS;      // [64][LDS]
    float*  Cs = (float*)sh;         // [64][LDS] floats (aliases Bs)

    int tid = threadIdx.x;
    int rbase = blockIdx.x * 64;

#pragma unroll
    for (int i = 0; i < 8; i++) {
        int f = tid + i * 256;
        int row = f >> 4, c8 = f & 15;
        *(uint4*)&Bs[row * LDS + c8 * 8] = ((const uint4*)(B + row * HD))[c8];
    }
#pragma unroll
    for (int i = 0; i < 4; i++) {
        int f = tid + i * 256;
        int row = f >> 4, c8 = f & 15;
        int gr = rbase + row;
        uint4 v = make_uint4(0u, 0u, 0u, 0u);
        if (gr < nrows) v = ((const uint4*)(A + gr * HD))[c8];
        *(uint4*)&As[row * LDS + c8 * 8] = v;
    }
    __syncthreads();

    int wid = tid >> 5;
    int wr = (wid >> 1) * 16;
    int wc = (wid & 1) * 64;

    wmma::fragment<wmma::accumulator, 16, 16, 16, float> acc[4];
#pragma unroll
    for (int c = 0; c < 4; c++) wmma::fill_fragment(acc[c], 0.f);

#pragma unroll
    for (int k = 0; k < HD; k += 16) {
        wmma::fragment<wmma::matrix_a, 16, 16, 16, __half, wmma::row_major> af;
        wmma::load_matrix_sync(af, As + wr * LDS + k, LDS);
#pragma unroll
        for (int c = 0; c < 4; c++) {
            wmma::fragment<wmma::matrix_b, 16, 16, 16, __half, wmma::row_major> bf;
            wmma::load_matrix_sync(bf, Bs + k * LDS + wc + c * 16, LDS);
            wmma::mma_sync(acc[c], af, bf, acc[c]);
        }
    }
    __syncthreads();

#pragma unroll
    for (int c = 0; c < 4; c++)
        wmma::store_matrix_sync(Cs + wr * LDS + wc + c * 16, acc[c], LDS, wmma::mem_row_major);
    __syncthreads();

#pragma unroll
    for (int i = 0; i < 8; i++) {
        int f = tid + i * 256;
        int row = f >> 5, c4 = (f & 31) * 4;
        int gr = rbase + row;
        if (gr < nrows) {
            float4 v = *(float4*)&Cs[row * LDS + c4];
            __half2 p0 = __floats2half2_rn(v.x, v.y);
            __half2 p1 = __floats2half2_rn(v.z, v.w);
            uint2 pk;
            pk.x = *(unsigned*)&p0;
            pk.y = *(unsigned*)&p1;
            *(uint2*)&S[gr * HD + c4] = pk;
        }
    }
}

// ---------------- aggregation: out[n] = relu(b + sum_e w_e * Sh[src_e]) ---
// one warp per dst node; 8-deep unroll; packed csr; fused slin epilogue
__global__ void agg_kernel(const __half* __restrict__ Sh,
                           const float* __restrict__ bias,
                           __half* __restrict__ out,
                           const float* __restrict__ wa, int layer) {
    int w = (blockIdx.x * blockDim.x + threadIdx.x) >> 5;
    int lane = threadIdx.x & 31;
    if (w >= NN) return;
    int beg = g_off[w], end = g_off[w + 1];
    int c0 = lane * 4;
    float4 acc = make_float4(0.f, 0.f, 0.f, 0.f);

    int e = beg;
    for (; e + 7 < end; e += 8) {
        int2 pr[8];
        uint2 p[8];
#pragma unroll
        for (int j = 0; j < 8; j++) pr[j] = g_csr[e + j];
#pragma unroll
        for (int j = 0; j < 8; j++) p[j] = *(const uint2*)&Sh[pr[j].x * HD + c0];
#pragma unroll
        for (int j = 0; j < 8; j++) {
            float wj = __int_as_float(pr[j].y);
            float2 a = __half22float2(*(__half2*)&p[j].x);
            float2 b = __half22float2(*(__half2*)&p[j].y);
            acc.x = fmaf(wj, a.x, acc.x); acc.y = fmaf(wj, a.y, acc.y);
            acc.z = fmaf(wj, b.x, acc.z); acc.w = fmaf(wj, b.y, acc.w);
        }
    }
    for (; e < end; e++) {
        int2 pr = g_csr[e];
        float wj = __int_as_float(pr.y);
        uint2 p = *(const uint2*)&Sh[pr.x * HD + c0];
        float2 a = __half22float2(*(__half2*)&p.x);
        float2 b = __half22float2(*(__half2*)&p.y);
        acc.x = fmaf(wj, a.x, acc.x); acc.y = fmaf(wj, a.y, acc.y);
        acc.z = fmaf(wj, b.x, acc.z); acc.w = fmaf(wj, b.y, acc.w);
    }
    float4 bb = *(const float4*)&bias[c0];
    acc.x = fmaxf(acc.x + bb.x, 0.f);
    acc.y = fmaxf(acc.y + bb.y, 0.f);
    acc.z = fmaxf(acc.z + bb.z, 0.f);
    acc.w = fmaxf(acc.w + bb.w, 0.f);
    __half2 o0 = __floats2half2_rn(acc.x, acc.y);
    __half2 o1 = __floats2half2_rn(acc.z, acc.w);
    uint2 pk;
    pk.x = *(unsigned*)&o0;
    pk.y = *(unsigned*)&o1;
    *(uint2*)&out[w * HD + c0] = pk;

    float4 wv = *(const float4*)&wa[layer * HD + c0];
    float part = acc.x * wv.x + acc.y * wv.y + acc.z * wv.z + acc.w * wv.w;
#pragma unroll
    for (int o = 16; o > 0; o >>= 1) part += __shfl_down_sync(0xffffffffu, part, o);
    if (lane == 0) {
        if (layer == 0) g_slin[w] = part;
        else            g_slin[w] += part;
    }
}

// ---------------- pool (score fused): per (graph, stripe) block -----------
// phase 1: compute score = tanh(agg(slin) + ba) for this block's nodes
// phase 2: sum + max of h*score per graph
__global__ void pool_kernel(const float* __restrict__ ba) {
    int g = blockIdx.x, y = blockIdx.y;
    int beg = g_gstart[g], end = g_gstart[g + 1];
    __shared__ float sc[3264];
    int span = end - beg - y;
    int L = (span > 0) ? (span + 15) / 16 : 0;
    float ba0 = ba[0];

    for (int k = threadIdx.x; k < L; k += 384) {
        int n = beg + y + 16 * k;
        float r = 0.f;
        int b2 = g_off[n], e2 = g_off[n + 1];
        for (int e = b2; e < e2; e++) {
            int2 pr = g_csr[e];
            r = fmaf(__int_as_float(pr.y), g_slin[pr.x], r);
        }
        sc[k] = tanhf(r + ba0);
    }
    __syncthreads();

    int c = threadIdx.x;  // 0..383
    const __half* A = (c < 128) ? g_h1 : (c < 256) ? g_h2 : g_h3;
    int cc = c & 127;
    float sum = 0.f, mx = -3.4e38f;
    for (int k = 0; k < L; k++) {
        int n = beg + y + 16 * k;
        float v = __half2float(A[n * HD + cc]) * sc[k];
        sum += v;
        mx = fmaxf(mx, v);
    }
    atomicAdd(&g_poolsum[g * 384 + c], sum);
    atomicMax(&g_poolmax[g * 384 + c], encf(mx));
}

// ---------------- final: relu([avg, max] @ Wf + bf) -----------------------
__global__ void final_kernel(const float* __restrict__ Wf,
                             const float* __restrict__ bf,
                             float* __restrict__ out) {
    int g = blockIdx.x, j = threadIdx.x;  // 128 threads
    __shared__ float p[768];
    float cnt = (float)(g_gstart[g + 1] - g_gstart[g]);
    float inv = 1.f / fmaxf(cnt, 1.f);
    for (int k = j; k < 768; k += 128)
        p[k] = (k < 384) ? g_poolsum[g * 384 + k] * inv
                         : decf(g_poolmax[g * 384 + (k - 384)]);
    __syncthreads();
    float acc = bf[j];
#pragma unroll 8
    for (int k = 0; k < 768; k++)
        acc = fmaf(p[k], Wf[k * HD + j], acc);
    out[g * HD + j] = fmaxf(acc, 0.f);
}

// ---------------- launch ----------------
extern "C" void kernel_launch(void* const* d_in, const int* in_sizes, int n_in,
                              void* d_out, int out_size) {
    const int* ei   = (const int*)d_in[0];
    const float* ew = (const float*)d_in[1];
    const float* X  = (const float*)d_in[2];
    const int* gi   = (const int*)d_in[3];
    const float* W1 = (const float*)d_in[4];
    const float* b1 = (const float*)d_in[5];
    const float* W2 = (const float*)d_in[6];
    const float* b2 = (const float*)d_in[7];
    const float* W3 = (const float*)d_in[8];
    const float* b3 = (const float*)d_in[9];
    const float* wa = (const float*)d_in[10];
    const float* ba = (const float*)d_in[11];
    const float* Wf = (const float*)d_in[12];
    const float* bf = (const float*)d_in[13];
    float* out = (float*)d_out;

    static cudaStream_t s1 = nullptr;
    static cudaEvent_t ev_fork = nullptr, ev_join = nullptr, ev_pool = nullptr;
    static bool attr_done = false;
    if (!s1) {
        cudaStreamCreateWithFlags(&s1, cudaStreamNonBlocking);
        cudaEventCreateWithFlags(&ev_fork, cudaEventDisableTiming);
        cudaEventCreateWithFlags(&ev_join, cudaEventDisableTiming);
        cudaEventCreateWithFlags(&ev_pool, cudaEventDisableTiming);
    }
    const int SMEM_GEMM = (HD * LDS + 64 * LDS) * 2;  // 52224 bytes
    if (!attr_done) {
        cudaFuncSetAttribute(gemm128h_kernel,
                             cudaFuncAttributeMaxDynamicSharedMemorySize, SMEM_GEMM);
        attr_done = true;
    }

    void *pS, *pXh, *pWh, *ph1, *ph2, *ph3, *pdeg;
    cudaGetSymbolAddress(&pS,  g_Sh);
    cudaGetSymbolAddress(&pXh, g_Xh);
    cudaGetSymbolAddress(&pWh, g_Wh);
    cudaGetSymbolAddress(&ph1, g_h1);
    cudaGetSymbolAddress(&ph2, g_h2);
    cudaGetSymbolAddress(&ph3, g_h3);
    cudaGetSymbolAddress(&pdeg, g_deg);
    __half* S  = (__half*)pS;
    __half* Xh = (__half*)pXh;
    __half* Wh = (__half*)pWh;
    __half* h1 = (__half*)ph1;
    __half* h2 = (__half*)ph2;
    __half* h3 = (__half*)ph3;

    const int NB = (NN + 255) / 256;
    const int GEMM_GRID = (NN + 63) / 64;
    const int AGG_GRID = (NN * 32 + 255) / 256;
    const int WQ = (HD * HD) / 4;
    const int XQ = (NN * HD) / 4;

    // fork: conversions + GEMM1 + pool-side init on s1, parallel with CSR build
    cudaEventRecord(ev_fork, 0);
    cudaStreamWaitEvent(s1, ev_fork, 0);
    f2h_kernel<<<(WQ + 255) / 256, 256, 0, s1>>>(W1, Wh,               WQ);
    f2h_kernel<<<(WQ + 255) / 256, 256, 0, s1>>>(W2, Wh + HD * HD,     WQ);
    f2h_kernel<<<(WQ + 255) / 256, 256, 0, s1>>>(W3, Wh + 2 * HD * HD, WQ);
    f2h_kernel<<<(XQ + 255) / 256, 256, 0, s1>>>(X, Xh, XQ);
    gemm128h_kernel<<<GEMM_GRID, 256, SMEM_GEMM, s1>>>(Xh, Wh, S, NN);
    cudaEventRecord(ev_join, s1);
    zero_pool_kernel<<<64, 384, 0, s1>>>();
    bounds_kernel<<<NB, 256, 0, s1>>>(gi);
    bounds_fix_kernel<<<1, 32, 0, s1>>>();
    cudaEventRecord(ev_pool, s1);

    // CSR build chain on the capture (null) stream
    cudaMemsetAsync(pdeg, 0, NN * sizeof(int), 0);
    hist_kernel<<<(NE / 4 + 255) / 256, 256>>>(ei);
    scan_part_kernel<<<SCAN_BLKS, 1024>>>();
    scan_final_kernel<<<SCAN_BLKS, 1024>>>();
    scatter_kernel<<<(NE / 2 + 255) / 256, 256>>>(ei, ew);

    // join: agg1 needs both CSR and S
    cudaStreamWaitEvent(0, ev_join, 0);
    agg_kernel<<<AGG_GRID, 256>>>(S, b1, h1, wa, 0);

    gemm128h_kernel<<<GEMM_GRID, 256, SMEM_GEMM>>>(h1, Wh + HD * HD, S, NN);
    agg_kernel<<<AGG_GRID, 256>>>(S, b2, h2, wa, 1);

    gemm128h_kernel<<<GEMM_GRID, 256, SMEM_GEMM>>>(h2, Wh + 2 * HD * HD, S, NN);
    agg_kernel<<<AGG_GRID, 256>>>(S, b3, h3, wa, 2);

    cudaStreamWaitEvent(0, ev_pool, 0);
    pool_kernel<<<dim3(NG, 16), 384>>>(ba);
    final_kernel<<<NG, 128>>>(Wf, bf, out);
}

// round 16
// speedup vs baseline: 1.2758x; 1.2758x over previous
#include <cuda_runtime.h>
#include <cuda_fp16.h>
#include <mma.h>
#include <math.h>

using namespace nvcuda;

#define NN 50000
#define NE 800000
#define HD 128
#define NG 64
#define SCAN_BLKS 49   // 49*1024 >= NN
#define LDS 136        // padded smem leading dim (halves / floats)

// ---------------- scratch (device globals: allocation-free) ----------------
__device__ int      g_deg[NN];
__device__ int      g_fill[NN];
__device__ int      g_off[NN + 1];
__device__ int      g_bsum[SCAN_BLKS];
__device__ int      g_csr_src[NE];
__device__ float    g_csr_w[NE];
__device__ __half   g_Sh[NN * HD];     // GEMM output (support), fp16
__device__ __half   g_Xh[NN * HD];     // fp16 copy of input features
__device__ __half   g_Wh[3 * HD * HD]; // fp16 copies of W1,W2,W3
__device__ __half   g_h1[NN * HD];     // layer outputs, fp16
__device__ __half   g_h2[NN * HD];
__device__ __half   g_h3[NN * HD];
__device__ float    g_slin[NN];
__device__ float    g_score[NN];
__device__ float    g_poolsum[NG * 3 * HD];
__device__ unsigned g_poolmax[NG * 3 * HD];
__device__ int      g_gstart[NG + 1];

// monotonic float<->uint encoding for atomicMax on floats
__device__ __forceinline__ unsigned encf(float f) {
    unsigned u = __float_as_uint(f);
    return (u & 0x80000000u) ? ~u : (u | 0x80000000u);
}
__device__ __forceinline__ float decf(unsigned u) {
    return __uint_as_float((u & 0x80000000u) ? (u ^ 0x80000000u) : ~u);
}

// ---------------- fp32 -> fp16 conversion (vectorized) ---------------------
__global__ void f2h_kernel(const float* __restrict__ in, __half* __restrict__ out, int n4) {
    int i = blockIdx.x * blockDim.x + threadIdx.x;
    if (i >= n4) return;
    float4 v = ((const float4*)in)[i];
    __half2 p0 = __floats2half2_rn(v.x, v.y);
    __half2 p1 = __floats2half2_rn(v.z, v.w);
    uint2 pk;
    pk.x = *(unsigned*)&p0;
    pk.y = *(unsigned*)&p1;
    ((uint2*)out)[i] = pk;
}

// ---------------- init (pool-side; runs off critical path) ----------------
__global__ void zero_pool_kernel() {
    int i = blockIdx.x * blockDim.x + threadIdx.x;
    int stride = gridDim.x * blockDim.x;
    for (int j = i; j < NG * 3 * HD; j += stride) { g_poolsum[j] = 0.f; g_poolmax[j] = 0u; }
    if (i < NG + 1) g_gstart[i] = 0;
}

// ---------------- CSR build (edge_index int32) -----------------------------
// 4 edges per thread via int4
__global__ void hist_kernel(const int* __restrict__ ei) {
    int i = blockIdx.x * blockDim.x + threadIdx.x;
    if (i >= NE / 4) return;
    int4 d4 = ((const int4*)(ei + NE))[i];
    if ((unsigned)d4.x < NN) atomicAdd(&g_deg[d4.x], 1);
    if ((unsigned)d4.y < NN) atomicAdd(&g_deg[d4.y], 1);
    if ((unsigned)d4.z < NN) atomicAdd(&g_deg[d4.z], 1);
    if ((unsigned)d4.w < NN) atomicAdd(&g_deg[d4.w], 1);
}

__global__ void scan_part_kernel() {
    int idx = blockIdx.x * 1024 + threadIdx.x;
    int v = (idx < NN) ? g_deg[idx] : 0;
    int lane = threadIdx.x & 31, wid = threadIdx.x >> 5;
#pragma unroll
    for (int o = 16; o > 0; o >>= 1) v += __shfl_down_sync(0xffffffffu, v, o);
    __shared__ int ws[32];
    if (lane == 0) ws[wid] = v;
    __syncthreads();
    if (wid == 0) {
        int s = ws[lane];
#pragma unroll
        for (int o = 16; o > 0; o >>= 1) s += __shfl_down_sync(0xffffffffu, s, o);
        if (lane == 0) g_bsum[blockIdx.x] = s;
    }
}

__global__ void scan_final_kernel() {
    int t = threadIdx.x;
    int idx = blockIdx.x * 1024 + t;
    int v = (idx < NN) ? g_deg[idx] : 0;
    int lane = t & 31, wid = t >> 5;

    __shared__ int bs[64];
    __shared__ int ws[32];
    __shared__ int base_sh;
    if (t < SCAN_BLKS) bs[t] = g_bsum[t];

    int incl = v;
#pragma unroll
    for (int o = 1; o < 32; o <<= 1) {
        int x = __shfl_up_sync(0xffffffffu, incl, o);
        if (lane >= o) incl += x;
    }
    if (lane == 31) ws[wid] = incl;
    __syncthreads();
    if (wid == 0) {
        int s = (lane < 32) ? ws[lane] : 0;
#pragma unroll
        for (int o = 1; o < 32; o <<= 1) {
            int x = __shfl_up_sync(0xffffffffu, s, o);
            if (lane >= o) s += x;
        }
        ws[lane] = s;
    }
    if (t == 0) {
        int b = 0;
        for (int i = 0; i < blockIdx.x; i++) b += bs[i];
        base_sh = b;
    }
    __syncthreads();
    int warpbase = (wid > 0) ? ws[wid - 1] : 0;
    int excl = base_sh + warpbase + incl - v;
    if (idx < NN) { g_off[idx] = excl; g_fill[idx] = excl; }
    if (blockIdx.x == gridDim.x - 1 && t == 1023) g_off[NN] = base_sh + warpbase + incl;
}

__global__ void scatter_kernel(const int* __restrict__ ei,
                               const float* __restrict__ ew) {
    int e = blockIdx.x * blockDim.x + threadIdx.x;
    if (e >= NE) return;
    unsigned d = (unsigned)ei[NE + e];
    unsigned s = (unsigned)ei[e];
    if (d >= NN || s >= NN) return;
    int pos = atomicAdd(&g_fill[d], 1);
    g_csr_src[pos] = (int)s;
    g_csr_w[pos] = ew[e];
}

__global__ void bounds_kernel(const int* __restrict__ gi) {
    int n = blockIdx.x * blockDim.x + threadIdx.x;
    if (n >= NN) return;
    int g = gi[n];
    if ((unsigned)g >= NG) return;
    if (n == 0) g_gstart[g] = 0;
    else if (gi[n - 1] != g) g_gstart[g] = n;
    if (n == NN - 1) g_gstart[NG] = NN;
}

__global__ void bounds_fix_kernel() {
    if (threadIdx.x == 0) {
        for (int g = NG - 1; g >= 1; g--)
            if (g_gstart[g] == 0 && g_gstart[g - 1] != 0) g_gstart[g] = g_gstart[g + 1];
    }
}

// ---------------- GEMM: Sh = fp16( A(fp16) @ W(fp16) ), fp32 accumulate ---
// wmma m16n16k16; block = 256 threads (8 warps), tile = 64 rows x 128 cols.
// Smem tiles padded to LDS=136 to avoid bank conflicts.
__global__ void __launch_bounds__(256)
gemm128h_kernel(const __half* __restrict__ A,
                const __half* __restrict__ B,
                __half* __restrict__ S, int nrows) {
    extern __shared__ __half sh[];
    __half* Bs = sh;                 // [128][LDS]
    __half* As = sh + HD * LDS;      // [64][LDS]
    float*  Cs = (float*)sh;         // [64][LDS] floats (aliases Bs)

    int tid = threadIdx.x;
    int rbase = blockIdx.x * 64;

#pragma unroll
    for (int i = 0; i < 8; i++) {
        int f = tid + i * 256;
        int row = f >> 4, c8 = f & 15;
        *(uint4*)&Bs[row * LDS + c8 * 8] = ((const uint4*)(B + row * HD))[c8];
    }
#pragma unroll
    for (int i = 0; i < 4; i++) {
        int f = tid + i * 256;
        int row = f >> 4, c8 = f & 15;
        int gr = rbase + row;
        uint4 v = make_uint4(0u, 0u, 0u, 0u);
        if (gr < nrows) v = ((const uint4*)(A + gr * HD))[c8];
        *(uint4*)&As[row * LDS + c8 * 8] = v;
    }
    __syncthreads();

    int wid = tid >> 5;
    int wr = (wid >> 1) * 16;
    int wc = (wid & 1) * 64;

    wmma::fragment<wmma::accumulator, 16, 16, 16, float> acc[4];
#pragma unroll
    for (int c = 0; c < 4; c++) wmma::fill_fragment(acc[c], 0.f);

#pragma unroll
    for (int k = 0; k < HD; k += 16) {
        wmma::fragment<wmma::matrix_a, 16, 16, 16, __half, wmma::row_major> af;
        wmma::load_matrix_sync(af, As + wr * LDS + k, LDS);
#pragma unroll
        for (int c = 0; c < 4; c++) {
            wmma::fragment<wmma::matrix_b, 16, 16, 16, __half, wmma::row_major> bf;
            wmma::load_matrix_sync(bf, Bs + k * LDS + wc + c * 16, LDS);
            wmma::mma_sync(acc[c], af, bf, acc[c]);
        }
    }
    __syncthreads();

#pragma unroll
    for (int c = 0; c < 4; c++)
        wmma::store_matrix_sync(Cs + wr * LDS + wc + c * 16, acc[c], LDS, wmma::mem_row_major);
    __syncthreads();

#pragma unroll
    for (int i = 0; i < 8; i++) {
        int f = tid + i * 256;
        int row = f >> 5, c4 = (f & 31) * 4;
        int gr = rbase + row;
        if (gr < nrows) {
            float4 v = *(float4*)&Cs[row * LDS + c4];
            __half2 p0 = __floats2half2_rn(v.x, v.y);
            __half2 p1 = __floats2half2_rn(v.z, v.w);
            uint2 pk;
            pk.x = *(unsigned*)&p0;
            pk.y = *(unsigned*)&p1;
            *(uint2*)&S[gr * HD + c4] = pk;
        }
    }
}

// ---------------- aggregation: out[n] = relu(b + sum_e w_e * Sh[src_e]) ---
__global__ void agg_kernel(const __half* __restrict__ Sh,
                           const float* __restrict__ bias,
                           __half* __restrict__ out,
                           const float* __restrict__ wa, int layer) {
    int w = (blockIdx.x * blockDim.x + threadIdx.x) >> 5;
    int lane = threadIdx.x & 31;
    if (w >= NN) return;
    int beg = g_off[w], end = g_off[w + 1];
    int c0 = lane * 4;
    float4 acc = make_float4(0.f, 0.f, 0.f, 0.f);

    int e = beg;
    for (; e + 3 < end; e += 4) {
        int s0 = g_csr_src[e],     s1 = g_csr_src[e + 1];
        int s2 = g_csr_src[e + 2], s3 = g_csr_src[e + 3];
        float w0 = g_csr_w[e],     w1 = g_csr_w[e + 1];
        float w2 = g_csr_w[e + 2], w3 = g_csr_w[e + 3];
        uint2 p0 = *(const uint2*)&Sh[s0 * HD + c0];
        uint2 p1 = *(const uint2*)&Sh[s1 * HD + c0];
        uint2 p2 = *(const uint2*)&Sh[s2 * HD + c0];
        uint2 p3 = *(const uint2*)&Sh[s3 * HD + c0];
        float2 a0 = __half22float2(*(__half2*)&p0.x), b0 = __half22float2(*(__half2*)&p0.y);
        float2 a1 = __half22float2(*(__half2*)&p1.x), b1 = __half22float2(*(__half2*)&p1.y);
        float2 a2 = __half22float2(*(__half2*)&p2.x), b2 = __half22float2(*(__half2*)&p2.y);
        float2 a3 = __half22float2(*(__half2*)&p3.x), b3 = __half22float2(*(__half2*)&p3.y);
        acc.x = fmaf(w0, a0.x, acc.x); acc.y = fmaf(w0, a0.y, acc.y);
        acc.z = fmaf(w0, b0.x, acc.z); acc.w = fmaf(w0, b0.y, acc.w);
        acc.x = fmaf(w1, a1.x, acc.x); acc.y = fmaf(w1, a1.y, acc.y);
        acc.z = fmaf(w1, b1.x, acc.z); acc.w = fmaf(w1, b1.y, acc.w);
        acc.x = fmaf(w2, a2.x, acc.x); acc.y = fmaf(w2, a2.y, acc.y);
        acc.z = fmaf(w2, b2.x, acc.z); acc.w = fmaf(w2, b2.y, acc.w);
        acc.x = fmaf(w3, a3.x, acc.x); acc.y = fmaf(w3, a3.y, acc.y);
        acc.z = fmaf(w3, b3.x, acc.z); acc.w = fmaf(w3, b3.y, acc.w);
    }
    for (; e < end; e++) {
        int s0 = g_csr_src[e];
        float w0 = g_csr_w[e];
        uint2 p0 = *(const uint2*)&Sh[s0 * HD + c0];
        float2 a0 = __half22float2(*(__half2*)&p0.x), b0 = __half22float2(*(__half2*)&p0.y);
        acc.x = fmaf(w0, a0.x, acc.x); acc.y = fmaf(w0, a0.y, acc.y);
        acc.z = fmaf(w0, b0.x, acc.z); acc.w = fmaf(w0, b0.y, acc.w);
    }
    float4 bb = *(const float4*)&bias[c0];
    acc.x = fmaxf(acc.x + bb.x, 0.f);
    acc.y = fmaxf(acc.y + bb.y, 0.f);
    acc.z = fmaxf(acc.z + bb.z, 0.f);
    acc.w = fmaxf(acc.w + bb.w, 0.f);
    __half2 o0 = __floats2half2_rn(acc.x, acc.y);
    __half2 o1 = __floats2half2_rn(acc.z, acc.w);
    uint2 pk;
    pk.x = *(unsigned*)&o0;
    pk.y = *(unsigned*)&o1;
    *(uint2*)&out[w * HD + c0] = pk;

    float4 wv = *(const float4*)&wa[layer * HD + c0];
    float part = acc.x * wv.x + acc.y * wv.y + acc.z * wv.z + acc.w * wv.w;
#pragma unroll
    for (int o = 16; o > 0; o >>= 1) part += __shfl_down_sync(0xffffffffu, part, o);
    if (lane == 0) {
        if (layer == 0) g_slin[w] = part;
        else            g_slin[w] += part;
    }
}

// ---------------- score: tanh(segsum(w_e * slin[src]) + ba) ----------------
__global__ void score_kernel(const float* __restrict__ ba) {
    int n = blockIdx.x * blockDim.x + threadIdx.x;
    if (n >= NN) return;
    float r = 0.f;
    int beg = g_off[n], end = g_off[n + 1];
    for (int e = beg; e < end; e++)
        r = fmaf(g_csr_w[e], g_slin[g_csr_src[e]], r);
    g_score[n] = tanhf(r + ba[0]);
}

// ---------------- segment pooling (sum + max of h*score per graph) --------
__global__ void pool_kernel() {
    int g = blockIdx.x;
    int beg = g_gstart[g], end = g_gstart[g + 1];
    int c = threadIdx.x;  // 0..383
    const __half* A = (c < 128) ? g_h1 : (c < 256) ? g_h2 : g_h3;
    int cc = c & 127;
    float sum = 0.f, mx = -3.4e38f;
    for (int n = beg + blockIdx.y; n < end; n += gridDim.y) {
        float v = __half2float(A[n * HD + cc]) * g_score[n];
        sum += v;
        mx = fmaxf(mx, v);
    }
    atomicAdd(&g_poolsum[g * 384 + c], sum);
    atomicMax(&g_poolmax[g * 384 + c], encf(mx));
}

// ---------------- final: relu([avg, max] @ Wf + bf) -----------------------
__global__ void final_kernel(const float* __restrict__ Wf,
                             const float* __restrict__ bf,
                             float* __restrict__ out) {
    int g = blockIdx.x, j = threadIdx.x;  // 128 threads
    __shared__ float p[768];
    float cnt = (float)(g_gstart[g + 1] - g_gstart[g]);
    float inv = 1.f / fmaxf(cnt, 1.f);
    for (int k = j; k < 768; k += 128)
        p[k] = (k < 384) ? g_poolsum[g * 384 + k] * inv
                         : decf(g_poolmax[g * 384 + (k - 384)]);
    __syncthreads();
    float acc = bf[j];
#pragma unroll 8
    for (int k = 0; k < 768; k++)
        acc = fmaf(p[k], Wf[k * HD + j], acc);
    out[g * HD + j] = fmaxf(acc, 0.f);
}

// ---------------- launch ----------------
extern "C" void kernel_launch(void* const* d_in, const int* in_sizes, int n_in,
                              void* d_out, int out_size) {
    const int* ei   = (const int*)d_in[0];
    const float* ew = (const float*)d_in[1];
    const float* X  = (const float*)d_in[2];
    const int* gi   = (const int*)d_in[3];
    const float* W1 = (const float*)d_in[4];
    const float* b1 = (const float*)d_in[5];
    const float* W2 = (const float*)d_in[6];
    const float* b2 = (const float*)d_in[7];
    const float* W3 = (const float*)d_in[8];
    const float* b3 = (const float*)d_in[9];
    const float* wa = (const float*)d_in[10];
    const float* ba = (const float*)d_in[11];
    const float* Wf = (const float*)d_in[12];
    const float* bf = (const float*)d_in[13];
    float* out = (float*)d_out;

    static cudaStream_t s1 = nullptr;
    static cudaEvent_t ev_fork = nullptr, ev_join = nullptr, ev_pool = nullptr;
    static bool attr_done = false;
    if (!s1) {
        cudaStreamCreateWithFlags(&s1, cudaStreamNonBlocking);
        cudaEventCreateWithFlags(&ev_fork, cudaEventDisableTiming);
        cudaEventCreateWithFlags(&ev_join, cudaEventDisableTiming);
        cudaEventCreateWithFlags(&ev_pool, cudaEventDisableTiming);
    }
    const int SMEM_GEMM = (HD * LDS + 64 * LDS) * 2;  // 52224 bytes
    if (!attr_done) {
        cudaFuncSetAttribute(gemm128h_kernel,
                             cudaFuncAttributeMaxDynamicSharedMemorySize, SMEM_GEMM);
        attr_done = true;
    }

    void *pS, *pXh, *pWh, *ph1, *ph2, *ph3, *pdeg;
    cudaGetSymbolAddress(&pS,  g_Sh);
    cudaGetSymbolAddress(&pXh, g_Xh);
    cudaGetSymbolAddress(&pWh, g_Wh);
    cudaGetSymbolAddress(&ph1, g_h1);
    cudaGetSymbolAddress(&ph2, g_h2);
    cudaGetSymbolAddress(&ph3, g_h3);
    cudaGetSymbolAddress(&pdeg, g_deg);
    __half* S  = (__half*)pS;
    __half* Xh = (__half*)pXh;
    __half* Wh = (__half*)pWh;
    __half* h1 = (__half*)ph1;
    __half* h2 = (__half*)ph2;
    __half* h3 = (__half*)ph3;

    const int NB = (NN + 255) / 256;
    const int GEMM_GRID = (NN + 63) / 64;
    const int AGG_GRID = (NN * 32 + 255) / 256;
    const int WQ = (HD * HD) / 4;
    const int XQ = (NN * HD) / 4;

    // fork: conversions + GEMM1 + pool-side init on s1, parallel with CSR build
    cudaEventRecord(ev_fork, 0);
    cudaStreamWaitEvent(s1, ev_fork, 0);
    f2h_kernel<<<(WQ + 255) / 256, 256, 0, s1>>>(W1, Wh,               WQ);
    f2h_kernel<<<(WQ + 255) / 256, 256, 0, s1>>>(W2, Wh + HD * HD,     WQ);
    f2h_kernel<<<(WQ + 255) / 256, 256, 0, s1>>>(W3, Wh + 2 * HD * HD, WQ);
    f2h_kernel<<<(XQ + 255) / 256, 256, 0, s1>>>(X, Xh, XQ);
    gemm128h_kernel<<<GEMM_GRID, 256, SMEM_GEMM, s1>>>(Xh, Wh, S, NN);
    cudaEventRecord(ev_join, s1);
    zero_pool_kernel<<<64, 384, 0, s1>>>();
    bounds_kernel<<<NB, 256, 0, s1>>>(gi);
    bounds_fix_kernel<<<1, 32, 0, s1>>>();
    cudaEventRecord(ev_pool, s1);

    // CSR build chain on the capture (null) stream
    cudaMemsetAsync(pdeg, 0, NN * sizeof(int), 0);
    hist_kernel<<<(NE / 4 + 255) / 256, 256>>>(ei);
    scan_part_kernel<<<SCAN_BLKS, 1024>>>();
    scan_final_kernel<<<SCAN_BLKS, 1024>>>();
    scatter_kernel<<<(NE + 255) / 256, 256>>>(ei, ew);

    // join: agg1 needs both CSR and S
    cudaStreamWaitEvent(0, ev_join, 0);
    agg_kernel<<<AGG_GRID, 256>>>(S, b1, h1, wa, 0);

    gemm128h_kernel<<<GEMM_GRID, 256, SMEM_GEMM>>>(h1, Wh + HD * HD, S, NN);
    agg_kernel<<<AGG_GRID, 256>>>(S, b2, h2, wa, 1);

    gemm128h_kernel<<<GEMM_GRID, 256, SMEM_GEMM>>>(h2, Wh + 2 * HD * HD, S, NN);
    agg_kernel<<<AGG_GRID, 256>>>(S, b3, h3, wa, 2);

    score_kernel<<<NB, 256>>>(ba);
    cudaStreamWaitEvent(0, ev_pool, 0);
    pool_kernel<<<dim3(NG, 16), 384>>>();
    final_kernel<<<NG, 128>>>(Wf, bf, out);
}